// round 8
// baseline (speedup 1.0000x reference)
#include <cuda_runtime.h>
#include <cuda_bf16.h>
#include <math.h>
#include <cstdint>
#include <stdint.h>

// Problem constants
#define L_    32768
#define C_    512
#define H_    8
#define D_    64
#define E_    1048576
#define HID_  1024

typedef __nv_bfloat16 bf16_t;

// ---------------------------------------------------------------------------
// Scratch (device globals; no allocation allowed)
// ---------------------------------------------------------------------------
__device__ bf16_t g_zb[(size_t)L_ * C_];     // LN output (bf16, reused)
__device__ float  g_q[(size_t)L_ * C_];      // Q f32
__device__ bf16_t g_kb[(size_t)L_ * C_];     // K bf16
__device__ bf16_t g_vb[(size_t)L_ * C_];     // V bf16
__device__ bf16_t g_attb[(size_t)L_ * C_];   // attention output (bf16)
__device__ bf16_t g_hb[(size_t)L_ * HID_];   // MLP hidden (bf16)
__device__ bf16_t g_wq[C_ * C_], g_wk[C_ * C_], g_wv[C_ * C_], g_wo[C_ * C_];
__device__ bf16_t g_w1[C_ * HID_];           // W1^T  [HID][C]
__device__ bf16_t g_w2[C_ * HID_];           // W2^T  [C][HID]
__device__ int    g_seg[L_ + 1];

// ---------------------------------------------------------------------------
// Weight transpose + cast: W (K x N, f32) -> Wt (N x K, bf16)
// ---------------------------------------------------------------------------
__global__ __launch_bounds__(256) void wcast_kernel(
    const float* __restrict__ W, bf16_t* __restrict__ Wt, int K, int N)
{
    __shared__ float t[32][33];
    int n0 = blockIdx.x * 32, k0 = blockIdx.y * 32;
    int tx = threadIdx.x, ty = threadIdx.y;
    #pragma unroll
    for (int i = 0; i < 32; i += 8)
        t[ty + i][tx] = W[(size_t)(k0 + ty + i) * N + n0 + tx];
    __syncthreads();
    #pragma unroll
    for (int i = 0; i < 32; i += 8)
        Wt[(size_t)(n0 + ty + i) * K + k0 + tx] = __float2bfloat16_rn(t[tx][ty + i]);
}

// ---------------------------------------------------------------------------
// LayerNorm: one block (128 thr) per row, float4 per thread; bf16 output
// ---------------------------------------------------------------------------
__global__ __launch_bounds__(128) void ln_kernel(
    const float* __restrict__ x, const float* __restrict__ g,
    const float* __restrict__ b, bf16_t* __restrict__ z)
{
    int l = blockIdx.x, tid = threadIdx.x;
    float4 v = ((const float4*)(x + (size_t)l * C_))[tid];
    float s  = v.x + v.y + v.z + v.w;
    float ss = v.x * v.x + v.y * v.y + v.z * v.z + v.w * v.w;
    #pragma unroll
    for (int m = 16; m >= 1; m >>= 1) {
        s  += __shfl_xor_sync(0xffffffffu, s,  m);
        ss += __shfl_xor_sync(0xffffffffu, ss, m);
    }
    __shared__ float sb[4], ssb[4], stat[2];
    int wid = tid >> 5, lane = tid & 31;
    if (lane == 0) { sb[wid] = s; ssb[wid] = ss; }
    __syncthreads();
    if (tid == 0) {
        float S = sb[0] + sb[1] + sb[2] + sb[3];
        float SS = ssb[0] + ssb[1] + ssb[2] + ssb[3];
        float mu  = S * (1.f / 512.f);
        float var = SS * (1.f / 512.f) - mu * mu;
        stat[0] = mu;
        stat[1] = rsqrtf(var + 1e-5f);
    }
    __syncthreads();
    float mu = stat[0], rstd = stat[1];
    float4 gg = ((const float4*)g)[tid];
    float4 bb = ((const float4*)b)[tid];
    float o0 = (v.x - mu) * rstd * gg.x + bb.x;
    float o1 = (v.y - mu) * rstd * gg.y + bb.y;
    float o2 = (v.z - mu) * rstd * gg.z + bb.z;
    float o3 = (v.w - mu) * rstd * gg.w + bb.w;
    __nv_bfloat162 p0 = __floats2bfloat162_rn(o0, o1);
    __nv_bfloat162 p1 = __floats2bfloat162_rn(o2, o3);
    uint2 pk;
    pk.x = *(unsigned*)&p0;
    pk.y = *(unsigned*)&p1;
    ((uint2*)(z + (size_t)l * C_))[tid] = pk;
}

// ---------------------------------------------------------------------------
// Segment boundaries from sorted row_index
// ---------------------------------------------------------------------------
__global__ void seg_kernel(const int* __restrict__ row, int* __restrict__ seg)
{
    int e = blockIdx.x * blockDim.x + threadIdx.x;
    if (e >= E_) return;
    int r  = row[e];
    int rp = (e == 0) ? -1 : row[e - 1];
    for (int l = rp + 1; l <= r; l++) seg[l] = e;
    if (e == E_ - 1) {
        for (int l = r + 1; l <= L_; l++) seg[l] = E_;
    }
}

// ---------------------------------------------------------------------------
// Sparse attention: one block (256 thr = 8 warps) per destination row.
// Q f32, K/V bf16. Output bf16.
// ---------------------------------------------------------------------------
#define SMAX 256

__global__ __launch_bounds__(256) void attn_kernel(
    const float* __restrict__ Q, const bf16_t* __restrict__ K,
    const bf16_t* __restrict__ V, const float* __restrict__ bias,
    const int* __restrict__ col, const int* __restrict__ seg,
    bf16_t* __restrict__ out)
{
    __shared__ float sq[C_];
    __shared__ float sc[SMAX * H_];
    __shared__ float red[8 * C_];
    __shared__ float rm[H_], rs[H_], rf[H_];

    int l = blockIdx.x;
    int tid = threadIdx.x;
    int wid = tid >> 5, lane = tid & 31;
    int hsub = lane >> 3;

    {
        const float2* qr = (const float2*)(Q + (size_t)l * C_);
        float2 t = qr[tid];
        t.x *= 0.125f; t.y *= 0.125f;
        ((float2*)sq)[tid] = t;
    }
    if (tid < H_) { rm[tid] = -1e30f; rs[tid] = 0.f; }
    __syncthreads();

    int e0 = seg[l], e1 = seg[l + 1];

    float acc[16];
    #pragma unroll
    for (int i = 0; i < 16; i++) acc[i] = 0.f;

    const float4* sq4 = (const float4*)sq;

    for (int c0 = e0; c0 < e1; c0 += SMAX) {
        int cn = min(SMAX, e1 - c0);

        for (int i = wid; i < cn; i += 8) {
            int e  = c0 + i;
            int cx = col[e];
            const uint4* kp = (const uint4*)(K + (size_t)cx * C_);
            float pd[2];
            #pragma unroll
            for (int r = 0; r < 2; r++) {
                uint4 kk = kp[r * 32 + lane];
                const __nv_bfloat162* h2 = (const __nv_bfloat162*)&kk;
                float2 f0 = __bfloat1622float2(h2[0]);
                float2 f1 = __bfloat1622float2(h2[1]);
                float2 f2 = __bfloat1622float2(h2[2]);
                float2 f3 = __bfloat1622float2(h2[3]);
                const float4* qq = sq4 + (size_t)(r * 32 + lane) * 2;
                float4 q0 = qq[0], q1 = qq[1];
                pd[r] = q0.x * f0.x + q0.y * f0.y + q0.z * f1.x + q0.w * f1.y
                      + q1.x * f2.x + q1.y * f2.y + q1.z * f3.x + q1.w * f3.y;
            }
            #pragma unroll
            for (int m = 1; m < 8; m <<= 1) {
                #pragma unroll
                for (int r = 0; r < 2; r++)
                    pd[r] += __shfl_xor_sync(0xffffffffu, pd[r], m);
            }
            if ((lane & 7) == 0) {
                #pragma unroll
                for (int r = 0; r < 2; r++) {
                    int h = r * 4 + hsub;
                    sc[i * H_ + h] = pd[r] + bias[(size_t)e * H_ + h];
                }
            }
        }
        __syncthreads();

        {
            int h = wid;
            float mx = -1e30f;
            for (int i = lane; i < cn; i += 32) mx = fmaxf(mx, sc[i * H_ + h]);
            #pragma unroll
            for (int m = 16; m >= 1; m >>= 1)
                mx = fmaxf(mx, __shfl_xor_sync(0xffffffffu, mx, m));
            float oldm = rm[h];
            float newm = fmaxf(oldm, mx);
            float fac  = __expf(oldm - newm);
            float ps = 0.f;
            for (int i = lane; i < cn; i += 32) {
                float p = __expf(sc[i * H_ + h] - newm);
                sc[i * H_ + h] = p;
                ps += p;
            }
            #pragma unroll
            for (int m = 16; m >= 1; m >>= 1)
                ps += __shfl_xor_sync(0xffffffffu, ps, m);
            if (lane == 0) {
                rs[h] = rs[h] * fac + ps;
                rm[h] = newm;
                rf[h] = fac;
            }
        }
        __syncthreads();

        #pragma unroll
        for (int r = 0; r < 2; r++) {
            float f = rf[r * 4 + hsub];
            #pragma unroll
            for (int j = 0; j < 8; j++) acc[r * 8 + j] *= f;
        }

        for (int i = wid; i < cn; i += 8) {
            int e  = c0 + i;
            int cx = col[e];
            const uint4* vp = (const uint4*)(V + (size_t)cx * C_);
            #pragma unroll
            for (int r = 0; r < 2; r++) {
                float p = sc[i * H_ + r * 4 + hsub];
                uint4 vv = vp[r * 32 + lane];
                const __nv_bfloat162* h2 = (const __nv_bfloat162*)&vv;
                float2 f0 = __bfloat1622float2(h2[0]);
                float2 f1 = __bfloat1622float2(h2[1]);
                float2 f2 = __bfloat1622float2(h2[2]);
                float2 f3 = __bfloat1622float2(h2[3]);
                acc[r * 8 + 0] += p * f0.x;
                acc[r * 8 + 1] += p * f0.y;
                acc[r * 8 + 2] += p * f1.x;
                acc[r * 8 + 3] += p * f1.y;
                acc[r * 8 + 4] += p * f2.x;
                acc[r * 8 + 5] += p * f2.y;
                acc[r * 8 + 6] += p * f3.x;
                acc[r * 8 + 7] += p * f3.y;
            }
        }
        __syncthreads();
    }

    #pragma unroll
    for (int r = 0; r < 2; r++) {
        float4 t0 = make_float4(acc[r*8+0], acc[r*8+1], acc[r*8+2], acc[r*8+3]);
        float4 t1 = make_float4(acc[r*8+4], acc[r*8+5], acc[r*8+6], acc[r*8+7]);
        ((float4*)red)[wid * 128 + (r * 32 + lane) * 2 + 0] = t0;
        ((float4*)red)[wid * 128 + (r * 32 + lane) * 2 + 1] = t1;
    }
    __syncthreads();
    #pragma unroll
    for (int it = 0; it < 2; it++) {
        int d = tid + it * 256;
        float s = 0.f;
        #pragma unroll
        for (int w = 0; w < 8; w++) s += red[w * C_ + d];
        float den = rs[d >> 6];
        float o = (den > 0.f) ? s / den : 0.f;
        out[(size_t)l * C_ + d] = __float2bfloat16_rn(o);
    }
}

// ---------------------------------------------------------------------------
// BF16 tensor-core GEMM: 128x256 block tile, warptile 64x64, mma.m16n8k16,
// ldmatrix fragments, 4-stage cp.async pipeline, 1 CTA/SM.
// C = A(MxK) @ Bt^T + bias. A bf16 [M][K], Bt bf16 [N][K].
// EPI: 0 none, 1 SiLU, 2 +res.  OBF: 1 bf16 out, 0 f32 out.
// Requires M%128==0, N%256==0, K%32==0.
// ---------------------------------------------------------------------------
#define BKP 40
#define STG 4
#define ASTGB (128 * BKP * 2)            // A bytes per stage
#define BSTGB (256 * BKP * 2)            // B bytes per stage
#define HS_BYTES (STG * (ASTGB + BSTGB)) // 122880

__device__ __forceinline__ void cp16(uint32_t s, const void* g) {
    asm volatile("cp.async.cg.shared.global [%0], [%1], 16;\n"
                 :: "r"(s), "l"(g));
}

#define LDMX4(r0, r1, r2, r3, addr) \
    asm volatile("ldmatrix.sync.aligned.m8n8.x4.shared.b16 {%0,%1,%2,%3}, [%4];" \
                 : "=r"(r0), "=r"(r1), "=r"(r2), "=r"(r3) : "r"(addr))

template <int EPI, int OBF>
__global__ __launch_bounds__(256, 1) void hgemm_kernel(
    const bf16_t* __restrict__ A, const bf16_t* __restrict__ Bt,
    const float* __restrict__ bias, const float* __restrict__ res,
    void* __restrict__ Cout, int M, int N, int K)
{
    extern __shared__ bf16_t smem[];
    uint32_t uA = (uint32_t)__cvta_generic_to_shared(smem);
    uint32_t uB = uA + STG * ASTGB;

    int tid = threadIdx.x;
    int bx = blockIdx.x, by = blockIdx.y;
    int lane = tid & 31, wid = tid >> 5;
    int wm = (wid & 1) * 64, wn = (wid >> 1) * 64;
    int g = lane >> 2, t = lane & 3;

    const bf16_t* Arow = A  + (size_t)(by * 128) * K;
    const bf16_t* Brow = Bt + (size_t)(bx * 256) * K;

    // ldmatrix per-lane offsets (bytes, within a stage)
    int lq = lane >> 3, lr = lane & 7;
    int a_row = (lq & 1) * 8 + lr;
    int a_k   = (lq >> 1) * 8;
    uint32_t a_off[4];
    #pragma unroll
    for (int mi = 0; mi < 4; mi++)
        a_off[mi] = uA + ((wm + mi * 16 + a_row) * BKP + a_k) * 2;
    int b_row = (lq >> 1) * 8 + lr;
    int b_k   = (lq & 1) * 8;
    uint32_t b_off[4];
    #pragma unroll
    for (int p = 0; p < 4; p++)
        b_off[p] = uB + ((wn + p * 16 + b_row) * BKP + b_k) * 2;

    float acc[4][8][4];
    #pragma unroll
    for (int mi = 0; mi < 4; mi++)
        #pragma unroll
        for (int ni = 0; ni < 8; ni++)
            #pragma unroll
            for (int r = 0; r < 4; r++) acc[mi][ni][r] = 0.f;

    int KT = K >> 5;

    // staging: slab kt -> stage s. chunk c: row = c>>2, kc = (c&3)*8 elems.
    auto stage = [&](int kt, int s) {
        #pragma unroll
        for (int i = 0; i < 2; i++) {
            int c = tid + i * 256;
            int row = c >> 2, kc = (c & 3) * 8;
            cp16(uA + s * ASTGB + (row * BKP + kc) * 2,
                 Arow + (size_t)row * K + kt * 32 + kc);
        }
        #pragma unroll
        for (int i = 0; i < 4; i++) {
            int c = tid + i * 256;
            int row = c >> 2, kc = (c & 3) * 8;
            cp16(uB + s * BSTGB + (row * BKP + kc) * 2,
                 Brow + (size_t)row * K + kt * 32 + kc);
        }
        asm volatile("cp.async.commit_group;\n");
    };

    // prologue: stage slabs 0..2  (KT >= 16 for all our shapes)
    #pragma unroll
    for (int s = 0; s < 3; s++) stage(s, s);

    for (int kt = 0; kt < KT; kt++) {
        if (kt < KT - 2)       asm volatile("cp.async.wait_group 2;\n");
        else if (kt == KT - 2) asm volatile("cp.async.wait_group 1;\n");
        else                   asm volatile("cp.async.wait_group 0;\n");
        __syncthreads();

        int buf = kt & (STG - 1);
        uint32_t stA = buf * ASTGB, stB = buf * BSTGB;

        #pragma unroll
        for (int ks = 0; ks < 32; ks += 16) {
            unsigned af[4][4];
            unsigned bfr[4][4];
            #pragma unroll
            for (int mi = 0; mi < 4; mi++)
                LDMX4(af[mi][0], af[mi][1], af[mi][2], af[mi][3],
                      a_off[mi] + stA + ks * 2);
            #pragma unroll
            for (int p = 0; p < 4; p++)
                LDMX4(bfr[p][0], bfr[p][1], bfr[p][2], bfr[p][3],
                      b_off[p] + stB + ks * 2);
            #pragma unroll
            for (int mi = 0; mi < 4; mi++)
                #pragma unroll
                for (int ni = 0; ni < 8; ni++) {
                    int p = ni >> 1, hh = (ni & 1) * 2;
                    asm volatile(
                        "mma.sync.aligned.m16n8k16.row.col.f32.bf16.bf16.f32 "
                        "{%0,%1,%2,%3}, {%4,%5,%6,%7}, {%8,%9}, {%0,%1,%2,%3};\n"
                        : "+f"(acc[mi][ni][0]), "+f"(acc[mi][ni][1]),
                          "+f"(acc[mi][ni][2]), "+f"(acc[mi][ni][3])
                        : "r"(af[mi][0]), "r"(af[mi][1]),
                          "r"(af[mi][2]), "r"(af[mi][3]),
                          "r"(bfr[p][hh]), "r"(bfr[p][hh + 1]));
                }
        }

        if (kt + 3 < KT) stage(kt + 3, (kt + 3) & (STG - 1));
    }

    // epilogue
    #pragma unroll
    for (int mi = 0; mi < 4; mi++) {
        #pragma unroll
        for (int ni = 0; ni < 8; ni++) {
            int col = bx * 256 + wn + ni * 8 + 2 * t;
            float2 bb = *(const float2*)&bias[col];
            #pragma unroll
            for (int h = 0; h < 2; h++) {
                int row = by * 128 + wm + mi * 16 + g + h * 8;
                float v0 = acc[mi][ni][2 * h + 0] + bb.x;
                float v1 = acc[mi][ni][2 * h + 1] + bb.y;
                if (EPI == 1) {
                    v0 = v0 / (1.f + __expf(-v0));
                    v1 = v1 / (1.f + __expf(-v1));
                }
                if (EPI == 2) {
                    float2 rr = *(const float2*)&res[(size_t)row * N + col];
                    v0 += rr.x; v1 += rr.y;
                }
                if (OBF) {
                    *(__nv_bfloat162*)((bf16_t*)Cout + (size_t)row * N + col) =
                        __floats2bfloat162_rn(v0, v1);
                } else {
                    *(float2*)((float*)Cout + (size_t)row * N + col) =
                        make_float2(v0, v1);
                }
            }
        }
    }
}

// ---------------------------------------------------------------------------
// Launch
// ---------------------------------------------------------------------------
extern "C" void kernel_launch(void* const* d_in, const int* in_sizes, int n_in,
                              void* d_out, int out_size)
{
    const float *x, *att_bias, *Wq, *bq, *Wk, *bk, *Wv, *bv, *Wo, *bo;
    const float *ln1g, *ln1b, *ln2g, *ln2b, *W1, *b1, *W2, *b2;
    const int *row, *col;

    if (in_sizes[1] == E_ * H_) {
        x        = (const float*)d_in[0];
        att_bias = (const float*)d_in[1];
        Wq = (const float*)d_in[2];  bq = (const float*)d_in[3];
        Wk = (const float*)d_in[4];  bk = (const float*)d_in[5];
        Wv = (const float*)d_in[6];  bv = (const float*)d_in[7];
        Wo = (const float*)d_in[8];  bo = (const float*)d_in[9];
        ln1g = (const float*)d_in[10]; ln1b = (const float*)d_in[11];
        ln2g = (const float*)d_in[12]; ln2b = (const float*)d_in[13];
        W1 = (const float*)d_in[14]; b1 = (const float*)d_in[15];
        W2 = (const float*)d_in[16]; b2 = (const float*)d_in[17];
        row = (const int*)d_in[18];  col = (const int*)d_in[19];
    } else {
        x   = (const float*)d_in[0];
        row = (const int*)d_in[1];
        col = (const int*)d_in[2];
        att_bias = (const float*)d_in[3];
        Wq = (const float*)d_in[4];  bq = (const float*)d_in[5];
        Wk = (const float*)d_in[6];  bk = (const float*)d_in[7];
        Wv = (const float*)d_in[8];  bv = (const float*)d_in[9];
        Wo = (const float*)d_in[10]; bo = (const float*)d_in[11];
        ln1g = (const float*)d_in[12]; ln1b = (const float*)d_in[13];
        ln2g = (const float*)d_in[14]; ln2b = (const float*)d_in[15];
        W1 = (const float*)d_in[16]; b1 = (const float*)d_in[17];
        W2 = (const float*)d_in[18]; b2 = (const float*)d_in[19];
    }

    bf16_t *pz, *pkb, *pvb, *pa, *ph, *pwq, *pwk, *pwv, *pwo, *pw1, *pw2;
    float *pq;
    int* pseg;
    cudaGetSymbolAddress((void**)&pz,  g_zb);
    cudaGetSymbolAddress((void**)&pq,  g_q);
    cudaGetSymbolAddress((void**)&pkb, g_kb);
    cudaGetSymbolAddress((void**)&pvb, g_vb);
    cudaGetSymbolAddress((void**)&pa,  g_attb);
    cudaGetSymbolAddress((void**)&ph,  g_hb);
    cudaGetSymbolAddress((void**)&pwq, g_wq);
    cudaGetSymbolAddress((void**)&pwk, g_wk);
    cudaGetSymbolAddress((void**)&pwv, g_wv);
    cudaGetSymbolAddress((void**)&pwo, g_wo);
    cudaGetSymbolAddress((void**)&pw1, g_w1);
    cudaGetSymbolAddress((void**)&pw2, g_w2);
    cudaGetSymbolAddress((void**)&pseg, g_seg);

    static bool attr_done = false;
    if (!attr_done) {
        cudaFuncSetAttribute(hgemm_kernel<0,0>, cudaFuncAttributeMaxDynamicSharedMemorySize, HS_BYTES);
        cudaFuncSetAttribute(hgemm_kernel<0,1>, cudaFuncAttributeMaxDynamicSharedMemorySize, HS_BYTES);
        cudaFuncSetAttribute(hgemm_kernel<2,0>, cudaFuncAttributeMaxDynamicSharedMemorySize, HS_BYTES);
        cudaFuncSetAttribute(hgemm_kernel<1,1>, cudaFuncAttributeMaxDynamicSharedMemorySize, HS_BYTES);
        attr_done = true;
    }

    float* out = (float*)d_out;

    dim3 t32(32, 8);
    // 0. weight transpose+cast to bf16
    wcast_kernel<<<dim3(C_ / 32, C_ / 32), t32>>>(Wq, pwq, C_, C_);
    wcast_kernel<<<dim3(C_ / 32, C_ / 32), t32>>>(Wk, pwk, C_, C_);
    wcast_kernel<<<dim3(C_ / 32, C_ / 32), t32>>>(Wv, pwv, C_, C_);
    wcast_kernel<<<dim3(C_ / 32, C_ / 32), t32>>>(Wo, pwo, C_, C_);
    wcast_kernel<<<dim3(HID_ / 32, C_ / 32), t32>>>(W1, pw1, C_, HID_);
    wcast_kernel<<<dim3(C_ / 32, HID_ / 32), t32>>>(W2, pw2, HID_, C_);

    // 1. z = LN1(x)  (bf16)
    ln_kernel<<<L_, 128>>>(x, ln1g, ln1b, pz);
    // 2. segment boundaries
    seg_kernel<<<E_ / 256, 256>>>(row, pseg);
    // 3. q (f32), k, v (bf16) projections
    dim3 gC(C_ / 256, L_ / 128);
    hgemm_kernel<0, 0><<<gC, 256, HS_BYTES>>>(pz, pwq, bq, nullptr, pq, L_, C_, C_);
    hgemm_kernel<0, 1><<<gC, 256, HS_BYTES>>>(pz, pwk, bk, nullptr, pkb, L_, C_, C_);
    hgemm_kernel<0, 1><<<gC, 256, HS_BYTES>>>(pz, pwv, bv, nullptr, pvb, L_, C_, C_);
    // 4. sparse attention (bf16 K/V gather, bf16 out)
    attn_kernel<<<L_, 256>>>(pq, pkb, pvb, att_bias, col, pseg, pa);
    // 5. out = x + att @ Wo + bo   (f32 out)
    hgemm_kernel<2, 0><<<gC, 256, HS_BYTES>>>(pa, pwo, bo, x, out, L_, C_, C_);
    // 6. z = LN2(out)  (bf16)
    ln_kernel<<<L_, 128>>>(out, ln2g, ln2b, pz);
    // 7. h = silu(z @ W1 + b1)  (bf16 out)
    dim3 gH(HID_ / 256, L_ / 128);
    hgemm_kernel<1, 1><<<gH, 256, HS_BYTES>>>(pz, pw1, b1, nullptr, ph, L_, HID_, C_);
    // 8. out = out + h @ W2 + b2  (f32 out, in-place residual)
    hgemm_kernel<2, 0><<<gC, 256, HS_BYTES>>>(ph, pw2, b2, out, out, L_, C_, HID_);
}

// round 9
// speedup vs baseline: 1.0734x; 1.0734x over previous
#include <cuda_runtime.h>
#include <cuda_bf16.h>
#include <math.h>
#include <cstdint>
#include <stdint.h>

// Problem constants
#define L_    32768
#define C_    512
#define H_    8
#define D_    64
#define E_    1048576
#define HID_  1024
#define QKV3  1536

typedef __nv_bfloat16 bf16_t;

// ---------------------------------------------------------------------------
// Scratch (device globals; no allocation allowed)
// ---------------------------------------------------------------------------
__device__ bf16_t g_zb[(size_t)L_ * C_];      // LN output (bf16, reused)
__device__ bf16_t g_qkv[(size_t)L_ * QKV3];   // fused q|k|v rows (bf16)
__device__ bf16_t g_attb[(size_t)L_ * C_];    // attention output (bf16)
__device__ bf16_t g_hb[(size_t)L_ * HID_];    // MLP hidden (bf16)
__device__ bf16_t g_wqkv[QKV3 * C_];          // fused Wqkv^T [1536][512]
__device__ bf16_t g_wo[C_ * C_];
__device__ bf16_t g_w1[C_ * HID_];            // W1^T  [HID][C]
__device__ bf16_t g_w2[C_ * HID_];            // W2^T  [C][HID]
__device__ float  g_bqkv[QKV3];               // fused bias
__device__ int    g_seg[L_ + 1];

// ---------------------------------------------------------------------------
// Weight transpose + cast: W (K x N, f32) -> Wt (N x K, bf16)
// ---------------------------------------------------------------------------
__global__ __launch_bounds__(256) void wcast_kernel(
    const float* __restrict__ W, bf16_t* __restrict__ Wt, int K, int N)
{
    __shared__ float t[32][33];
    int n0 = blockIdx.x * 32, k0 = blockIdx.y * 32;
    int tx = threadIdx.x, ty = threadIdx.y;
    #pragma unroll
    for (int i = 0; i < 32; i += 8)
        t[ty + i][tx] = W[(size_t)(k0 + ty + i) * N + n0 + tx];
    __syncthreads();
    #pragma unroll
    for (int i = 0; i < 32; i += 8)
        Wt[(size_t)(n0 + ty + i) * K + k0 + tx] = __float2bfloat16_rn(t[tx][ty + i]);
}

// concat 3 bias vectors of length C_ into one of length 3C
__global__ void bcat_kernel(const float* __restrict__ a,
                            const float* __restrict__ b,
                            const float* __restrict__ c,
                            float* __restrict__ o)
{
    int i = blockIdx.x * blockDim.x + threadIdx.x;
    if (i < C_) { o[i] = a[i]; o[C_ + i] = b[i]; o[2 * C_ + i] = c[i]; }
}

// ---------------------------------------------------------------------------
// LayerNorm: one block (128 thr) per row, float4 per thread; bf16 output
// ---------------------------------------------------------------------------
__global__ __launch_bounds__(128) void ln_kernel(
    const float* __restrict__ x, const float* __restrict__ g,
    const float* __restrict__ b, bf16_t* __restrict__ z)
{
    int l = blockIdx.x, tid = threadIdx.x;
    float4 v = ((const float4*)(x + (size_t)l * C_))[tid];
    float s  = v.x + v.y + v.z + v.w;
    float ss = v.x * v.x + v.y * v.y + v.z * v.z + v.w * v.w;
    #pragma unroll
    for (int m = 16; m >= 1; m >>= 1) {
        s  += __shfl_xor_sync(0xffffffffu, s,  m);
        ss += __shfl_xor_sync(0xffffffffu, ss, m);
    }
    __shared__ float sb[4], ssb[4], stat[2];
    int wid = tid >> 5, lane = tid & 31;
    if (lane == 0) { sb[wid] = s; ssb[wid] = ss; }
    __syncthreads();
    if (tid == 0) {
        float S = sb[0] + sb[1] + sb[2] + sb[3];
        float SS = ssb[0] + ssb[1] + ssb[2] + ssb[3];
        float mu  = S * (1.f / 512.f);
        float var = SS * (1.f / 512.f) - mu * mu;
        stat[0] = mu;
        stat[1] = rsqrtf(var + 1e-5f);
    }
    __syncthreads();
    float mu = stat[0], rstd = stat[1];
    float4 gg = ((const float4*)g)[tid];
    float4 bb = ((const float4*)b)[tid];
    float o0 = (v.x - mu) * rstd * gg.x + bb.x;
    float o1 = (v.y - mu) * rstd * gg.y + bb.y;
    float o2 = (v.z - mu) * rstd * gg.z + bb.z;
    float o3 = (v.w - mu) * rstd * gg.w + bb.w;
    __nv_bfloat162 p0 = __floats2bfloat162_rn(o0, o1);
    __nv_bfloat162 p1 = __floats2bfloat162_rn(o2, o3);
    uint2 pk;
    pk.x = *(unsigned*)&p0;
    pk.y = *(unsigned*)&p1;
    ((uint2*)(z + (size_t)l * C_))[tid] = pk;
}

// ---------------------------------------------------------------------------
// Segment boundaries from sorted row_index
// ---------------------------------------------------------------------------
__global__ void seg_kernel(const int* __restrict__ row, int* __restrict__ seg)
{
    int e = blockIdx.x * blockDim.x + threadIdx.x;
    if (e >= E_) return;
    int r  = row[e];
    int rp = (e == 0) ? -1 : row[e - 1];
    for (int l = rp + 1; l <= r; l++) seg[l] = e;
    if (e == E_ - 1) {
        for (int l = r + 1; l <= L_; l++) seg[l] = E_;
    }
}

// ---------------------------------------------------------------------------
// Sparse attention: one block (256 thr = 8 warps) per destination row.
// q/k/v all bf16, fused rows of g_qkv: [q(512) | k(512) | v(512)].
// Output bf16.
// ---------------------------------------------------------------------------
#define SMAX 256

__global__ __launch_bounds__(256) void attn_kernel(
    const bf16_t* __restrict__ QKV, const float* __restrict__ bias,
    const int* __restrict__ col, const int* __restrict__ seg,
    bf16_t* __restrict__ out)
{
    __shared__ float sq[C_];
    __shared__ float sc[SMAX * H_];
    __shared__ float red[8 * C_];
    __shared__ float rm[H_], rs[H_], rf[H_];

    int l = blockIdx.x;
    int tid = threadIdx.x;
    int wid = tid >> 5, lane = tid & 31;
    int hsub = lane >> 3;

    {   // load q row (bf16), fold in 1/sqrt(D)=0.125
        __nv_bfloat162 qb = ((const __nv_bfloat162*)(QKV + (size_t)l * QKV3))[tid];
        float2 t = __bfloat1622float2(qb);
        t.x *= 0.125f; t.y *= 0.125f;
        ((float2*)sq)[tid] = t;
    }
    if (tid < H_) { rm[tid] = -1e30f; rs[tid] = 0.f; }
    __syncthreads();

    int e0 = seg[l], e1 = seg[l + 1];

    float acc[16];
    #pragma unroll
    for (int i = 0; i < 16; i++) acc[i] = 0.f;

    const float4* sq4 = (const float4*)sq;
    const bf16_t* Kb = QKV + C_;
    const bf16_t* Vb = QKV + 2 * C_;

    for (int c0 = e0; c0 < e1; c0 += SMAX) {
        int cn = min(SMAX, e1 - c0);

        for (int i = wid; i < cn; i += 8) {
            int e  = c0 + i;
            int cx = col[e];
            const uint4* kp = (const uint4*)(Kb + (size_t)cx * QKV3);
            float pd[2];
            #pragma unroll
            for (int r = 0; r < 2; r++) {
                uint4 kk = kp[r * 32 + lane];
                const __nv_bfloat162* h2 = (const __nv_bfloat162*)&kk;
                float2 f0 = __bfloat1622float2(h2[0]);
                float2 f1 = __bfloat1622float2(h2[1]);
                float2 f2 = __bfloat1622float2(h2[2]);
                float2 f3 = __bfloat1622float2(h2[3]);
                const float4* qq = sq4 + (size_t)(r * 32 + lane) * 2;
                float4 q0 = qq[0], q1 = qq[1];
                pd[r] = q0.x * f0.x + q0.y * f0.y + q0.z * f1.x + q0.w * f1.y
                      + q1.x * f2.x + q1.y * f2.y + q1.z * f3.x + q1.w * f3.y;
            }
            #pragma unroll
            for (int m = 1; m < 8; m <<= 1) {
                #pragma unroll
                for (int r = 0; r < 2; r++)
                    pd[r] += __shfl_xor_sync(0xffffffffu, pd[r], m);
            }
            if ((lane & 7) == 0) {
                #pragma unroll
                for (int r = 0; r < 2; r++) {
                    int h = r * 4 + hsub;
                    sc[i * H_ + h] = pd[r] + bias[(size_t)e * H_ + h];
                }
            }
        }
        __syncthreads();

        {
            int h = wid;
            float mx = -1e30f;
            for (int i = lane; i < cn; i += 32) mx = fmaxf(mx, sc[i * H_ + h]);
            #pragma unroll
            for (int m = 16; m >= 1; m >>= 1)
                mx = fmaxf(mx, __shfl_xor_sync(0xffffffffu, mx, m));
            float oldm = rm[h];
            float newm = fmaxf(oldm, mx);
            float fac  = __expf(oldm - newm);
            float ps = 0.f;
            for (int i = lane; i < cn; i += 32) {
                float p = __expf(sc[i * H_ + h] - newm);
                sc[i * H_ + h] = p;
                ps += p;
            }
            #pragma unroll
            for (int m = 16; m >= 1; m >>= 1)
                ps += __shfl_xor_sync(0xffffffffu, ps, m);
            if (lane == 0) {
                rs[h] = rs[h] * fac + ps;
                rm[h] = newm;
                rf[h] = fac;
            }
        }
        __syncthreads();

        #pragma unroll
        for (int r = 0; r < 2; r++) {
            float f = rf[r * 4 + hsub];
            #pragma unroll
            for (int j = 0; j < 8; j++) acc[r * 8 + j] *= f;
        }

        for (int i = wid; i < cn; i += 8) {
            int e  = c0 + i;
            int cx = col[e];
            const uint4* vp = (const uint4*)(Vb + (size_t)cx * QKV3);
            #pragma unroll
            for (int r = 0; r < 2; r++) {
                float p = sc[i * H_ + r * 4 + hsub];
                uint4 vv = vp[r * 32 + lane];
                const __nv_bfloat162* h2 = (const __nv_bfloat162*)&vv;
                float2 f0 = __bfloat1622float2(h2[0]);
                float2 f1 = __bfloat1622float2(h2[1]);
                float2 f2 = __bfloat1622float2(h2[2]);
                float2 f3 = __bfloat1622float2(h2[3]);
                acc[r * 8 + 0] += p * f0.x;
                acc[r * 8 + 1] += p * f0.y;
                acc[r * 8 + 2] += p * f1.x;
                acc[r * 8 + 3] += p * f1.y;
                acc[r * 8 + 4] += p * f2.x;
                acc[r * 8 + 5] += p * f2.y;
                acc[r * 8 + 6] += p * f3.x;
                acc[r * 8 + 7] += p * f3.y;
            }
        }
        __syncthreads();
    }

    #pragma unroll
    for (int r = 0; r < 2; r++) {
        float4 t0 = make_float4(acc[r*8+0], acc[r*8+1], acc[r*8+2], acc[r*8+3]);
        float4 t1 = make_float4(acc[r*8+4], acc[r*8+5], acc[r*8+6], acc[r*8+7]);
        ((float4*)red)[wid * 128 + (r * 32 + lane) * 2 + 0] = t0;
        ((float4*)red)[wid * 128 + (r * 32 + lane) * 2 + 1] = t1;
    }
    __syncthreads();
    #pragma unroll
    for (int it = 0; it < 2; it++) {
        int d = tid + it * 256;
        float s = 0.f;
        #pragma unroll
        for (int w = 0; w < 8; w++) s += red[w * C_ + d];
        float den = rs[d >> 6];
        float o = (den > 0.f) ? s / den : 0.f;
        out[(size_t)l * C_ + d] = __float2bfloat16_rn(o);
    }
}

// ---------------------------------------------------------------------------
// BF16 tensor-core GEMM (R7 config): 128x128 tile, warptile 64x32,
// mma.m16n8k16, ldmatrix fragments, 3-stage cp.async, 2 CTAs/SM.
// C = A(MxK) @ Bt^T + bias. A bf16 [M][K], Bt bf16 [N][K].
// EPI: 0 none, 1 SiLU, 2 +res.  OBF: 1 bf16 out, 0 f32 out.
// ---------------------------------------------------------------------------
#define BKP 40
#define STG 3
#define HS_BYTES (2 * STG * 128 * BKP * 2)

__device__ __forceinline__ void cp16(uint32_t s, const void* g) {
    asm volatile("cp.async.cg.shared.global [%0], [%1], 16;\n"
                 :: "r"(s), "l"(g));
}

#define LDMX4(r0, r1, r2, r3, addr) \
    asm volatile("ldmatrix.sync.aligned.m8n8.x4.shared.b16 {%0,%1,%2,%3}, [%4];" \
                 : "=r"(r0), "=r"(r1), "=r"(r2), "=r"(r3) : "r"(addr))

template <int EPI, int OBF>
__global__ __launch_bounds__(256, 2) void hgemm_kernel(
    const bf16_t* __restrict__ A, const bf16_t* __restrict__ Bt,
    const float* __restrict__ bias, const float* __restrict__ res,
    void* __restrict__ Cout, int M, int N, int K)
{
    extern __shared__ bf16_t smem[];
    bf16_t* As = smem;                       // [STG][128*BKP]
    bf16_t* Bs = smem + STG * 128 * BKP;

    int tid = threadIdx.x;
    int bx = blockIdx.x, by = blockIdx.y;
    int lane = tid & 31, wid = tid >> 5;
    int wm = (wid & 1) * 64, wn = (wid >> 1) * 32;
    int g = lane >> 2, t = lane & 3;

    int srow = tid >> 1;
    int skc  = (tid & 1) * 16;

    const bf16_t* Agp = A  + (size_t)(by * 128 + srow) * K + skc;
    const bf16_t* Bgp = Bt + (size_t)(bx * 128 + srow) * K + skc;
    uint32_t sa = (uint32_t)__cvta_generic_to_shared(As + srow * BKP + skc);
    uint32_t sb = (uint32_t)__cvta_generic_to_shared(Bs + srow * BKP + skc);
    const uint32_t stgb = 128 * BKP * 2;   // bytes per stage

    // ldmatrix per-lane address offsets (bytes, within a stage)
    uint32_t uA = (uint32_t)__cvta_generic_to_shared(As);
    uint32_t uB = (uint32_t)__cvta_generic_to_shared(Bs);
    int lq = lane >> 3, lr = lane & 7;
    int a_row = (lq & 1) * 8 + lr;
    int a_k   = (lq >> 1) * 8;
    uint32_t a_off[4];
    #pragma unroll
    for (int mi = 0; mi < 4; mi++)
        a_off[mi] = uA + ((wm + mi * 16 + a_row) * BKP + a_k) * 2;
    int b_row = (lq >> 1) * 8 + lr;
    int b_k   = (lq & 1) * 8;
    uint32_t b_off[2];
    #pragma unroll
    for (int p = 0; p < 2; p++)
        b_off[p] = uB + ((wn + p * 16 + b_row) * BKP + b_k) * 2;

    float acc[4][4][4];
    #pragma unroll
    for (int mi = 0; mi < 4; mi++)
        #pragma unroll
        for (int ni = 0; ni < 4; ni++)
            #pragma unroll
            for (int r = 0; r < 4; r++) acc[mi][ni][r] = 0.f;

    int KT = K >> 5;

    // prologue: issue slabs 0 and 1
    #pragma unroll
    for (int s = 0; s < 2; s++) {
        cp16(sa + s * stgb,      Agp + s * 32);
        cp16(sa + s * stgb + 16, Agp + s * 32 + 8);
        cp16(sb + s * stgb,      Bgp + s * 32);
        cp16(sb + s * stgb + 16, Bgp + s * 32 + 8);
        asm volatile("cp.async.commit_group;\n");
    }

    int buf = 0;
    for (int kt = 0; kt < KT; kt++) {
        if (kt + 1 < KT) {
            asm volatile("cp.async.wait_group 1;\n");
        } else {
            asm volatile("cp.async.wait_group 0;\n");
        }
        __syncthreads();

        uint32_t stoff = buf * stgb;

        #pragma unroll
        for (int ks = 0; ks < 32; ks += 16) {
            unsigned af[4][4];
            unsigned bfr[2][4];
            #pragma unroll
            for (int mi = 0; mi < 4; mi++)
                LDMX4(af[mi][0], af[mi][1], af[mi][2], af[mi][3],
                      a_off[mi] + stoff + ks * 2);
            #pragma unroll
            for (int p = 0; p < 2; p++)
                LDMX4(bfr[p][0], bfr[p][1], bfr[p][2], bfr[p][3],
                      b_off[p] + stoff + ks * 2);
            #pragma unroll
            for (int mi = 0; mi < 4; mi++)
                #pragma unroll
                for (int ni = 0; ni < 4; ni++) {
                    int p = ni >> 1, hh = (ni & 1) * 2;
                    asm volatile(
                        "mma.sync.aligned.m16n8k16.row.col.f32.bf16.bf16.f32 "
                        "{%0,%1,%2,%3}, {%4,%5,%6,%7}, {%8,%9}, {%0,%1,%2,%3};\n"
                        : "+f"(acc[mi][ni][0]), "+f"(acc[mi][ni][1]),
                          "+f"(acc[mi][ni][2]), "+f"(acc[mi][ni][3])
                        : "r"(af[mi][0]), "r"(af[mi][1]),
                          "r"(af[mi][2]), "r"(af[mi][3]),
                          "r"(bfr[p][hh]), "r"(bfr[p][hh + 1]));
                }
        }

        if (kt + 2 < KT) {
            int s = (kt + 2) % STG;
            cp16(sa + s * stgb,      Agp + (kt + 2) * 32);
            cp16(sa + s * stgb + 16, Agp + (kt + 2) * 32 + 8);
            cp16(sb + s * stgb,      Bgp + (kt + 2) * 32);
            cp16(sb + s * stgb + 16, Bgp + (kt + 2) * 32 + 8);
            asm volatile("cp.async.commit_group;\n");
        }
        buf = (buf + 1) % STG;
    }

    // epilogue
    #pragma unroll
    for (int mi = 0; mi < 4; mi++) {
        #pragma unroll
        for (int ni = 0; ni < 4; ni++) {
            int col = bx * 128 + wn + ni * 8 + 2 * t;
            float2 bb = *(const float2*)&bias[col];
            #pragma unroll
            for (int h = 0; h < 2; h++) {
                int row = by * 128 + wm + mi * 16 + g + h * 8;
                float v0 = acc[mi][ni][2 * h + 0] + bb.x;
                float v1 = acc[mi][ni][2 * h + 1] + bb.y;
                if (EPI == 1) {
                    v0 = v0 / (1.f + __expf(-v0));
                    v1 = v1 / (1.f + __expf(-v1));
                }
                if (EPI == 2) {
                    float2 rr = *(const float2*)&res[(size_t)row * N + col];
                    v0 += rr.x; v1 += rr.y;
                }
                if (OBF) {
                    *(__nv_bfloat162*)((bf16_t*)Cout + (size_t)row * N + col) =
                        __floats2bfloat162_rn(v0, v1);
                } else {
                    *(float2*)((float*)Cout + (size_t)row * N + col) =
                        make_float2(v0, v1);
                }
            }
        }
    }
}

// ---------------------------------------------------------------------------
// Launch
// ---------------------------------------------------------------------------
extern "C" void kernel_launch(void* const* d_in, const int* in_sizes, int n_in,
                              void* d_out, int out_size)
{
    const float *x, *att_bias, *Wq, *bq, *Wk, *bk, *Wv, *bv, *Wo, *bo;
    const float *ln1g, *ln1b, *ln2g, *ln2b, *W1, *b1, *W2, *b2;
    const int *row, *col;

    if (in_sizes[1] == E_ * H_) {
        x        = (const float*)d_in[0];
        att_bias = (const float*)d_in[1];
        Wq = (const float*)d_in[2];  bq = (const float*)d_in[3];
        Wk = (const float*)d_in[4];  bk = (const float*)d_in[5];
        Wv = (const float*)d_in[6];  bv = (const float*)d_in[7];
        Wo = (const float*)d_in[8];  bo = (const float*)d_in[9];
        ln1g = (const float*)d_in[10]; ln1b = (const float*)d_in[11];
        ln2g = (const float*)d_in[12]; ln2b = (const float*)d_in[13];
        W1 = (const float*)d_in[14]; b1 = (const float*)d_in[15];
        W2 = (const float*)d_in[16]; b2 = (const float*)d_in[17];
        row = (const int*)d_in[18];  col = (const int*)d_in[19];
    } else {
        x   = (const float*)d_in[0];
        row = (const int*)d_in[1];
        col = (const int*)d_in[2];
        att_bias = (const float*)d_in[3];
        Wq = (const float*)d_in[4];  bq = (const float*)d_in[5];
        Wk = (const float*)d_in[6];  bk = (const float*)d_in[7];
        Wv = (const float*)d_in[8];  bv = (const float*)d_in[9];
        Wo = (const float*)d_in[10]; bo = (const float*)d_in[11];
        ln1g = (const float*)d_in[12]; ln1b = (const float*)d_in[13];
        ln2g = (const float*)d_in[14]; ln2b = (const float*)d_in[15];
        W1 = (const float*)d_in[16]; b1 = (const float*)d_in[17];
        W2 = (const float*)d_in[18]; b2 = (const float*)d_in[19];
    }

    bf16_t *pz, *pqkv, *pa, *ph, *pwqkv, *pwo, *pw1, *pw2;
    float *pbqkv;
    int* pseg;
    cudaGetSymbolAddress((void**)&pz,    g_zb);
    cudaGetSymbolAddress((void**)&pqkv,  g_qkv);
    cudaGetSymbolAddress((void**)&pa,    g_attb);
    cudaGetSymbolAddress((void**)&ph,    g_hb);
    cudaGetSymbolAddress((void**)&pwqkv, g_wqkv);
    cudaGetSymbolAddress((void**)&pwo,   g_wo);
    cudaGetSymbolAddress((void**)&pw1,   g_w1);
    cudaGetSymbolAddress((void**)&pw2,   g_w2);
    cudaGetSymbolAddress((void**)&pbqkv, g_bqkv);
    cudaGetSymbolAddress((void**)&pseg,  g_seg);

    static bool attr_done = false;
    if (!attr_done) {
        cudaFuncSetAttribute(hgemm_kernel<0,1>, cudaFuncAttributeMaxDynamicSharedMemorySize, HS_BYTES);
        cudaFuncSetAttribute(hgemm_kernel<2,0>, cudaFuncAttributeMaxDynamicSharedMemorySize, HS_BYTES);
        cudaFuncSetAttribute(hgemm_kernel<1,1>, cudaFuncAttributeMaxDynamicSharedMemorySize, HS_BYTES);
        attr_done = true;
    }

    float* out = (float*)d_out;

    dim3 t32(32, 8);
    // 0. weight staging: fused Wqkv^T rows [q|k|v], plus Wo, W1, W2
    wcast_kernel<<<dim3(C_ / 32, C_ / 32), t32>>>(Wq, pwqkv,            C_, C_);
    wcast_kernel<<<dim3(C_ / 32, C_ / 32), t32>>>(Wk, pwqkv + C_ * C_,  C_, C_);
    wcast_kernel<<<dim3(C_ / 32, C_ / 32), t32>>>(Wv, pwqkv + 2*C_*C_,  C_, C_);
    wcast_kernel<<<dim3(C_ / 32, C_ / 32), t32>>>(Wo, pwo, C_, C_);
    wcast_kernel<<<dim3(HID_ / 32, C_ / 32), t32>>>(W1, pw1, C_, HID_);
    wcast_kernel<<<dim3(C_ / 32, HID_ / 32), t32>>>(W2, pw2, HID_, C_);
    bcat_kernel<<<2, 256>>>(bq, bk, bv, pbqkv);

    // 1. z = LN1(x)  (bf16)
    ln_kernel<<<L_, 128>>>(x, ln1g, ln1b, pz);
    // 2. segment boundaries
    seg_kernel<<<E_ / 256, 256>>>(row, pseg);
    // 3. fused qkv projection (bf16 out, N=1536)
    dim3 gQKV(QKV3 / 128, L_ / 128);
    hgemm_kernel<0, 1><<<gQKV, 256, HS_BYTES>>>(pz, pwqkv, pbqkv, nullptr, pqkv, L_, QKV3, C_);
    // 4. sparse attention (all-bf16 gather, bf16 out)
    attn_kernel<<<L_, 256>>>(pqkv, att_bias, col, pseg, pa);
    // 5. out = x + att @ Wo + bo   (f32 out)
    dim3 gC(C_ / 128, L_ / 128);
    hgemm_kernel<2, 0><<<gC, 256, HS_BYTES>>>(pa, pwo, bo, x, out, L_, C_, C_);
    // 6. z = LN2(out)  (bf16)
    ln_kernel<<<L_, 128>>>(out, ln2g, ln2b, pz);
    // 7. h = silu(z @ W1 + b1)  (bf16 out)
    dim3 gH(HID_ / 128, L_ / 128);
    hgemm_kernel<1, 1><<<gH, 256, HS_BYTES>>>(pz, pw1, b1, nullptr, ph, L_, HID_, C_);
    // 8. out = out + h @ W2 + b2  (f32 out, in-place residual)
    hgemm_kernel<2, 0><<<gC, 256, HS_BYTES>>>(ph, pw2, b2, out, out, L_, C_, HID_);
}

// round 10
// speedup vs baseline: 1.0754x; 1.0019x over previous
#include <cuda_runtime.h>
#include <cuda_bf16.h>
#include <math.h>
#include <cstdint>
#include <stdint.h>

// Problem constants
#define L_    32768
#define C_    512
#define H_    8
#define D_    64
#define E_    1048576
#define HID_  1024
#define QKV3  1536

typedef __nv_bfloat16 bf16_t;

// ---------------------------------------------------------------------------
// Scratch (device globals; no allocation allowed)
// ---------------------------------------------------------------------------
__device__ bf16_t g_zb[(size_t)L_ * C_];      // LN output (bf16, reused)
__device__ bf16_t g_qkv[(size_t)L_ * QKV3];   // fused q|k|v rows (bf16)
__device__ bf16_t g_attb[(size_t)L_ * C_];    // attention output (bf16)
__device__ bf16_t g_hb[(size_t)L_ * HID_];    // MLP hidden (bf16)
__device__ bf16_t g_wqkv[QKV3 * C_];          // fused Wqkv^T [1536][512]
__device__ bf16_t g_wo[C_ * C_];
__device__ bf16_t g_w1[C_ * HID_];            // W1^T  [HID][C]
__device__ bf16_t g_w2[C_ * HID_];            // W2^T  [C][HID]
__device__ float  g_bqkv[QKV3];               // fused bias
__device__ int    g_seg[L_ + 1];

// ---------------------------------------------------------------------------
// Batched weight transpose + cast helpers
// ---------------------------------------------------------------------------
__device__ __forceinline__ void wt_tile(
    const float* __restrict__ W, bf16_t* __restrict__ Wt,
    int K, int N, int n0, int k0, int tx, int ty, float (*t)[33])
{
    #pragma unroll
    for (int i = 0; i < 32; i += 8)
        t[ty + i][tx] = W[(size_t)(k0 + ty + i) * N + n0 + tx];
    __syncthreads();
    #pragma unroll
    for (int i = 0; i < 32; i += 8)
        Wt[(size_t)(n0 + ty + i) * K + k0 + tx] = __float2bfloat16_rn(t[tx][ty + i]);
}

// 4 square 512x512 weights: Wq,Wk,Wv -> g_wqkv (concatenated), Wo -> g_wo
__global__ __launch_bounds__(256) void wcast_sq_kernel(
    const float* __restrict__ Wq, const float* __restrict__ Wk,
    const float* __restrict__ Wv, const float* __restrict__ Wo,
    bf16_t* __restrict__ wqkv, bf16_t* __restrict__ wo)
{
    __shared__ float t[32][33];
    int job = blockIdx.x >> 4;               // 0..3
    int n0 = (blockIdx.x & 15) * 32, k0 = blockIdx.y * 32;
    int tx = threadIdx.x, ty = threadIdx.y;
    const float* W = (job == 0) ? Wq : (job == 1) ? Wk : (job == 2) ? Wv : Wo;
    bf16_t* Wt = (job == 3) ? wo : wqkv + job * C_ * C_;
    wt_tile(W, Wt, C_, C_, n0, k0, tx, ty, t);
}

// W1 (512x1024) and W2 (1024x512) -> transposed bf16
__global__ __launch_bounds__(256) void wcast_mlp_kernel(
    const float* __restrict__ W1, const float* __restrict__ W2,
    bf16_t* __restrict__ w1t, bf16_t* __restrict__ w2t)
{
    __shared__ float t[32][33];
    int idx = blockIdx.x;
    int tx = threadIdx.x, ty = threadIdx.y;
    if (idx < 512) {                 // W1: K=512, N=1024
        int n0 = (idx & 31) * 32, k0 = (idx >> 5) * 32;
        wt_tile(W1, w1t, C_, HID_, n0, k0, tx, ty, t);
    } else {                         // W2: K=1024, N=512
        int j = idx - 512;
        int n0 = (j & 15) * 32, k0 = (j >> 4) * 32;
        wt_tile(W2, w2t, HID_, C_, n0, k0, tx, ty, t);
    }
}

// concat 3 bias vectors of length C_ into one of length 3C
__global__ void bcat_kernel(const float* __restrict__ a,
                            const float* __restrict__ b,
                            const float* __restrict__ c,
                            float* __restrict__ o)
{
    int i = blockIdx.x * blockDim.x + threadIdx.x;
    if (i < C_) { o[i] = a[i]; o[C_ + i] = b[i]; o[2 * C_ + i] = c[i]; }
}

// ---------------------------------------------------------------------------
// LayerNorm: one block (128 thr) per row, float4 per thread; bf16 output
// ---------------------------------------------------------------------------
__global__ __launch_bounds__(128) void ln_kernel(
    const float* __restrict__ x, const float* __restrict__ g,
    const float* __restrict__ b, bf16_t* __restrict__ z)
{
    int l = blockIdx.x, tid = threadIdx.x;
    float4 v = ((const float4*)(x + (size_t)l * C_))[tid];
    float s  = v.x + v.y + v.z + v.w;
    float ss = v.x * v.x + v.y * v.y + v.z * v.z + v.w * v.w;
    #pragma unroll
    for (int m = 16; m >= 1; m >>= 1) {
        s  += __shfl_xor_sync(0xffffffffu, s,  m);
        ss += __shfl_xor_sync(0xffffffffu, ss, m);
    }
    __shared__ float sb[4], ssb[4], stat[2];
    int wid = tid >> 5, lane = tid & 31;
    if (lane == 0) { sb[wid] = s; ssb[wid] = ss; }
    __syncthreads();
    if (tid == 0) {
        float S = sb[0] + sb[1] + sb[2] + sb[3];
        float SS = ssb[0] + ssb[1] + ssb[2] + ssb[3];
        float mu  = S * (1.f / 512.f);
        float var = SS * (1.f / 512.f) - mu * mu;
        stat[0] = mu;
        stat[1] = rsqrtf(var + 1e-5f);
    }
    __syncthreads();
    float mu = stat[0], rstd = stat[1];
    float4 gg = ((const float4*)g)[tid];
    float4 bb = ((const float4*)b)[tid];
    float o0 = (v.x - mu) * rstd * gg.x + bb.x;
    float o1 = (v.y - mu) * rstd * gg.y + bb.y;
    float o2 = (v.z - mu) * rstd * gg.z + bb.z;
    float o3 = (v.w - mu) * rstd * gg.w + bb.w;
    __nv_bfloat162 p0 = __floats2bfloat162_rn(o0, o1);
    __nv_bfloat162 p1 = __floats2bfloat162_rn(o2, o3);
    uint2 pk;
    pk.x = *(unsigned*)&p0;
    pk.y = *(unsigned*)&p1;
    ((uint2*)(z + (size_t)l * C_))[tid] = pk;
}

// ---------------------------------------------------------------------------
// Segment boundaries from sorted row_index
// ---------------------------------------------------------------------------
__global__ void seg_kernel(const int* __restrict__ row, int* __restrict__ seg)
{
    int e = blockIdx.x * blockDim.x + threadIdx.x;
    if (e >= E_) return;
    int r  = row[e];
    int rp = (e == 0) ? -1 : row[e - 1];
    for (int l = rp + 1; l <= r; l++) seg[l] = e;
    if (e == E_ - 1) {
        for (int l = r + 1; l <= L_; l++) seg[l] = E_;
    }
}

// ---------------------------------------------------------------------------
// Sparse attention: one block (256 thr = 8 warps) per destination row.
// q/k/v all bf16, fused rows of g_qkv: [q(512) | k(512) | v(512)].
// ---------------------------------------------------------------------------
#define SMAX 256

__global__ __launch_bounds__(256) void attn_kernel(
    const bf16_t* __restrict__ QKV, const float* __restrict__ bias,
    const int* __restrict__ col, const int* __restrict__ seg,
    bf16_t* __restrict__ out)
{
    __shared__ float sq[C_];
    __shared__ float sc[SMAX * H_];
    __shared__ float red[8 * C_];
    __shared__ float rm[H_], rs[H_], rf[H_];

    int l = blockIdx.x;
    int tid = threadIdx.x;
    int wid = tid >> 5, lane = tid & 31;
    int hsub = lane >> 3;

    {
        __nv_bfloat162 qb = ((const __nv_bfloat162*)(QKV + (size_t)l * QKV3))[tid];
        float2 t = __bfloat1622float2(qb);
        t.x *= 0.125f; t.y *= 0.125f;
        ((float2*)sq)[tid] = t;
    }
    if (tid < H_) { rm[tid] = -1e30f; rs[tid] = 0.f; }
    __syncthreads();

    int e0 = seg[l], e1 = seg[l + 1];

    float acc[16];
    #pragma unroll
    for (int i = 0; i < 16; i++) acc[i] = 0.f;

    const float4* sq4 = (const float4*)sq;
    const bf16_t* Kb = QKV + C_;
    const bf16_t* Vb = QKV + 2 * C_;

    for (int c0 = e0; c0 < e1; c0 += SMAX) {
        int cn = min(SMAX, e1 - c0);

        for (int i = wid; i < cn; i += 8) {
            int e  = c0 + i;
            int cx = col[e];
            const uint4* kp = (const uint4*)(Kb + (size_t)cx * QKV3);
            float pd[2];
            #pragma unroll
            for (int r = 0; r < 2; r++) {
                uint4 kk = kp[r * 32 + lane];
                const __nv_bfloat162* h2 = (const __nv_bfloat162*)&kk;
                float2 f0 = __bfloat1622float2(h2[0]);
                float2 f1 = __bfloat1622float2(h2[1]);
                float2 f2 = __bfloat1622float2(h2[2]);
                float2 f3 = __bfloat1622float2(h2[3]);
                const float4* qq = sq4 + (size_t)(r * 32 + lane) * 2;
                float4 q0 = qq[0], q1 = qq[1];
                pd[r] = q0.x * f0.x + q0.y * f0.y + q0.z * f1.x + q0.w * f1.y
                      + q1.x * f2.x + q1.y * f2.y + q1.z * f3.x + q1.w * f3.y;
            }
            #pragma unroll
            for (int m = 1; m < 8; m <<= 1) {
                #pragma unroll
                for (int r = 0; r < 2; r++)
                    pd[r] += __shfl_xor_sync(0xffffffffu, pd[r], m);
            }
            if ((lane & 7) == 0) {
                #pragma unroll
                for (int r = 0; r < 2; r++) {
                    int h = r * 4 + hsub;
                    sc[i * H_ + h] = pd[r] + bias[(size_t)e * H_ + h];
                }
            }
        }
        __syncthreads();

        {
            int h = wid;
            float mx = -1e30f;
            for (int i = lane; i < cn; i += 32) mx = fmaxf(mx, sc[i * H_ + h]);
            #pragma unroll
            for (int m = 16; m >= 1; m >>= 1)
                mx = fmaxf(mx, __shfl_xor_sync(0xffffffffu, mx, m));
            float oldm = rm[h];
            float newm = fmaxf(oldm, mx);
            float fac  = __expf(oldm - newm);
            float ps = 0.f;
            for (int i = lane; i < cn; i += 32) {
                float p = __expf(sc[i * H_ + h] - newm);
                sc[i * H_ + h] = p;
                ps += p;
            }
            #pragma unroll
            for (int m = 16; m >= 1; m >>= 1)
                ps += __shfl_xor_sync(0xffffffffu, ps, m);
            if (lane == 0) {
                rs[h] = rs[h] * fac + ps;
                rm[h] = newm;
                rf[h] = fac;
            }
        }
        __syncthreads();

        #pragma unroll
        for (int r = 0; r < 2; r++) {
            float f = rf[r * 4 + hsub];
            #pragma unroll
            for (int j = 0; j < 8; j++) acc[r * 8 + j] *= f;
        }

        for (int i = wid; i < cn; i += 8) {
            int e  = c0 + i;
            int cx = col[e];
            const uint4* vp = (const uint4*)(Vb + (size_t)cx * QKV3);
            #pragma unroll
            for (int r = 0; r < 2; r++) {
                float p = sc[i * H_ + r * 4 + hsub];
                uint4 vv = vp[r * 32 + lane];
                const __nv_bfloat162* h2 = (const __nv_bfloat162*)&vv;
                float2 f0 = __bfloat1622float2(h2[0]);
                float2 f1 = __bfloat1622float2(h2[1]);
                float2 f2 = __bfloat1622float2(h2[2]);
                float2 f3 = __bfloat1622float2(h2[3]);
                acc[r * 8 + 0] += p * f0.x;
                acc[r * 8 + 1] += p * f0.y;
                acc[r * 8 + 2] += p * f1.x;
                acc[r * 8 + 3] += p * f1.y;
                acc[r * 8 + 4] += p * f2.x;
                acc[r * 8 + 5] += p * f2.y;
                acc[r * 8 + 6] += p * f3.x;
                acc[r * 8 + 7] += p * f3.y;
            }
        }
        __syncthreads();
    }

    #pragma unroll
    for (int r = 0; r < 2; r++) {
        float4 t0 = make_float4(acc[r*8+0], acc[r*8+1], acc[r*8+2], acc[r*8+3]);
        float4 t1 = make_float4(acc[r*8+4], acc[r*8+5], acc[r*8+6], acc[r*8+7]);
        ((float4*)red)[wid * 128 + (r * 32 + lane) * 2 + 0] = t0;
        ((float4*)red)[wid * 128 + (r * 32 + lane) * 2 + 1] = t1;
    }
    __syncthreads();
    #pragma unroll
    for (int it = 0; it < 2; it++) {
        int d = tid + it * 256;
        float s = 0.f;
        #pragma unroll
        for (int w = 0; w < 8; w++) s += red[w * C_ + d];
        float den = rs[d >> 6];
        float o = (den > 0.f) ? s / den : 0.f;
        out[(size_t)l * C_ + d] = __float2bfloat16_rn(o);
    }
}

// ---------------------------------------------------------------------------
// BF16 tensor-core GEMM: 128x128 tile, warptile 64x32, mma.m16n8k16,
// ldmatrix fragments, 4-stage cp.async pipeline (wait_group 2), 2 CTAs/SM.
// C = A(MxK) @ Bt^T + bias. A bf16 [M][K], Bt bf16 [N][K].
// EPI: 0 none, 1 SiLU, 2 +res.  OBF: 1 bf16 out, 0 f32 out.
// ---------------------------------------------------------------------------
#define BKP 40
#define STG 4
#define HS_BYTES (2 * STG * 128 * BKP * 2)   // 81920

__device__ __forceinline__ void cp16(uint32_t s, const void* g) {
    asm volatile("cp.async.cg.shared.global [%0], [%1], 16;\n"
                 :: "r"(s), "l"(g));
}

#define LDMX4(r0, r1, r2, r3, addr) \
    asm volatile("ldmatrix.sync.aligned.m8n8.x4.shared.b16 {%0,%1,%2,%3}, [%4];" \
                 : "=r"(r0), "=r"(r1), "=r"(r2), "=r"(r3) : "r"(addr))

template <int EPI, int OBF>
__global__ __launch_bounds__(256, 2) void hgemm_kernel(
    const bf16_t* __restrict__ A, const bf16_t* __restrict__ Bt,
    const float* __restrict__ bias, const float* __restrict__ res,
    void* __restrict__ Cout, int M, int N, int K)
{
    extern __shared__ bf16_t smem[];
    bf16_t* As = smem;                       // [STG][128*BKP]
    bf16_t* Bs = smem + STG * 128 * BKP;

    int tid = threadIdx.x;
    int bx = blockIdx.x, by = blockIdx.y;
    int lane = tid & 31, wid = tid >> 5;
    int wm = (wid & 1) * 64, wn = (wid >> 1) * 32;
    int g = lane >> 2, t = lane & 3;

    int srow = tid >> 1;
    int skc  = (tid & 1) * 16;

    const bf16_t* Agp = A  + (size_t)(by * 128 + srow) * K + skc;
    const bf16_t* Bgp = Bt + (size_t)(bx * 128 + srow) * K + skc;
    uint32_t sa = (uint32_t)__cvta_generic_to_shared(As + srow * BKP + skc);
    uint32_t sb = (uint32_t)__cvta_generic_to_shared(Bs + srow * BKP + skc);
    const uint32_t stgb = 128 * BKP * 2;   // bytes per stage

    uint32_t uA = (uint32_t)__cvta_generic_to_shared(As);
    uint32_t uB = (uint32_t)__cvta_generic_to_shared(Bs);
    int lq = lane >> 3, lr = lane & 7;
    int a_row = (lq & 1) * 8 + lr;
    int a_k   = (lq >> 1) * 8;
    uint32_t a_off[4];
    #pragma unroll
    for (int mi = 0; mi < 4; mi++)
        a_off[mi] = uA + ((wm + mi * 16 + a_row) * BKP + a_k) * 2;
    int b_row = (lq >> 1) * 8 + lr;
    int b_k   = (lq & 1) * 8;
    uint32_t b_off[2];
    #pragma unroll
    for (int p = 0; p < 2; p++)
        b_off[p] = uB + ((wn + p * 16 + b_row) * BKP + b_k) * 2;

    float acc[4][4][4];
    #pragma unroll
    for (int mi = 0; mi < 4; mi++)
        #pragma unroll
        for (int ni = 0; ni < 4; ni++)
            #pragma unroll
            for (int r = 0; r < 4; r++) acc[mi][ni][r] = 0.f;

    int KT = K >> 5;

    // prologue: issue slabs 0..2
    #pragma unroll
    for (int s = 0; s < 3; s++) {
        cp16(sa + s * stgb,      Agp + s * 32);
        cp16(sa + s * stgb + 16, Agp + s * 32 + 8);
        cp16(sb + s * stgb,      Bgp + s * 32);
        cp16(sb + s * stgb + 16, Bgp + s * 32 + 8);
        asm volatile("cp.async.commit_group;\n");
    }

    for (int kt = 0; kt < KT; kt++) {
        if (kt < KT - 2)       asm volatile("cp.async.wait_group 2;\n");
        else if (kt == KT - 2) asm volatile("cp.async.wait_group 1;\n");
        else                   asm volatile("cp.async.wait_group 0;\n");
        __syncthreads();

        uint32_t stoff = (kt & (STG - 1)) * stgb;

        #pragma unroll
        for (int ks = 0; ks < 32; ks += 16) {
            unsigned af[4][4];
            unsigned bfr[2][4];
            #pragma unroll
            for (int mi = 0; mi < 4; mi++)
                LDMX4(af[mi][0], af[mi][1], af[mi][2], af[mi][3],
                      a_off[mi] + stoff + ks * 2);
            #pragma unroll
            for (int p = 0; p < 2; p++)
                LDMX4(bfr[p][0], bfr[p][1], bfr[p][2], bfr[p][3],
                      b_off[p] + stoff + ks * 2);
            #pragma unroll
            for (int mi = 0; mi < 4; mi++)
                #pragma unroll
                for (int ni = 0; ni < 4; ni++) {
                    int p = ni >> 1, hh = (ni & 1) * 2;
                    asm volatile(
                        "mma.sync.aligned.m16n8k16.row.col.f32.bf16.bf16.f32 "
                        "{%0,%1,%2,%3}, {%4,%5,%6,%7}, {%8,%9}, {%0,%1,%2,%3};\n"
                        : "+f"(acc[mi][ni][0]), "+f"(acc[mi][ni][1]),
                          "+f"(acc[mi][ni][2]), "+f"(acc[mi][ni][3])
                        : "r"(af[mi][0]), "r"(af[mi][1]),
                          "r"(af[mi][2]), "r"(af[mi][3]),
                          "r"(bfr[p][hh]), "r"(bfr[p][hh + 1]));
                }
        }

        if (kt + 3 < KT) {
            int s = (kt + 3) & (STG - 1);
            cp16(sa + s * stgb,      Agp + (kt + 3) * 32);
            cp16(sa + s * stgb + 16, Agp + (kt + 3) * 32 + 8);
            cp16(sb + s * stgb,      Bgp + (kt + 3) * 32);
            cp16(sb + s * stgb + 16, Bgp + (kt + 3) * 32 + 8);
            asm volatile("cp.async.commit_group;\n");
        }
    }

    // epilogue
    #pragma unroll
    for (int mi = 0; mi < 4; mi++) {
        #pragma unroll
        for (int ni = 0; ni < 4; ni++) {
            int col = bx * 128 + wn + ni * 8 + 2 * t;
            float2 bb = *(const float2*)&bias[col];
            #pragma unroll
            for (int h = 0; h < 2; h++) {
                int row = by * 128 + wm + mi * 16 + g + h * 8;
                float v0 = acc[mi][ni][2 * h + 0] + bb.x;
                float v1 = acc[mi][ni][2 * h + 1] + bb.y;
                if (EPI == 1) {
                    v0 = v0 / (1.f + __expf(-v0));
                    v1 = v1 / (1.f + __expf(-v1));
                }
                if (EPI == 2) {
                    float2 rr = *(const float2*)&res[(size_t)row * N + col];
                    v0 += rr.x; v1 += rr.y;
                }
                if (OBF) {
                    *(__nv_bfloat162*)((bf16_t*)Cout + (size_t)row * N + col) =
                        __floats2bfloat162_rn(v0, v1);
                } else {
                    *(float2*)((float*)Cout + (size_t)row * N + col) =
                        make_float2(v0, v1);
                }
            }
        }
    }
}

// ---------------------------------------------------------------------------
// Launch
// ---------------------------------------------------------------------------
extern "C" void kernel_launch(void* const* d_in, const int* in_sizes, int n_in,
                              void* d_out, int out_size)
{
    const float *x, *att_bias, *Wq, *bq, *Wk, *bk, *Wv, *bv, *Wo, *bo;
    const float *ln1g, *ln1b, *ln2g, *ln2b, *W1, *b1, *W2, *b2;
    const int *row, *col;

    if (in_sizes[1] == E_ * H_) {
        x        = (const float*)d_in[0];
        att_bias = (const float*)d_in[1];
        Wq = (const float*)d_in[2];  bq = (const float*)d_in[3];
        Wk = (const float*)d_in[4];  bk = (const float*)d_in[5];
        Wv = (const float*)d_in[6];  bv = (const float*)d_in[7];
        Wo = (const float*)d_in[8];  bo = (const float*)d_in[9];
        ln1g = (const float*)d_in[10]; ln1b = (const float*)d_in[11];
        ln2g = (const float*)d_in[12]; ln2b = (const float*)d_in[13];
        W1 = (const float*)d_in[14]; b1 = (const float*)d_in[15];
        W2 = (const float*)d_in[16]; b2 = (const float*)d_in[17];
        row = (const int*)d_in[18];  col = (const int*)d_in[19];
    } else {
        x   = (const float*)d_in[0];
        row = (const int*)d_in[1];
        col = (const int*)d_in[2];
        att_bias = (const float*)d_in[3];
        Wq = (const float*)d_in[4];  bq = (const float*)d_in[5];
        Wk = (const float*)d_in[6];  bk = (const float*)d_in[7];
        Wv = (const float*)d_in[8];  bv = (const float*)d_in[9];
        Wo = (const float*)d_in[10]; bo = (const float*)d_in[11];
        ln1g = (const float*)d_in[12]; ln1b = (const float*)d_in[13];
        ln2g = (const float*)d_in[14]; ln2b = (const float*)d_in[15];
        W1 = (const float*)d_in[16]; b1 = (const float*)d_in[17];
        W2 = (const float*)d_in[18]; b2 = (const float*)d_in[19];
    }

    bf16_t *pz, *pqkv, *pa, *ph, *pwqkv, *pwo, *pw1, *pw2;
    float *pbqkv;
    int* pseg;
    cudaGetSymbolAddress((void**)&pz,    g_zb);
    cudaGetSymbolAddress((void**)&pqkv,  g_qkv);
    cudaGetSymbolAddress((void**)&pa,    g_attb);
    cudaGetSymbolAddress((void**)&ph,    g_hb);
    cudaGetSymbolAddress((void**)&pwqkv, g_wqkv);
    cudaGetSymbolAddress((void**)&pwo,   g_wo);
    cudaGetSymbolAddress((void**)&pw1,   g_w1);
    cudaGetSymbolAddress((void**)&pw2,   g_w2);
    cudaGetSymbolAddress((void**)&pbqkv, g_bqkv);
    cudaGetSymbolAddress((void**)&pseg,  g_seg);

    static bool attr_done = false;
    if (!attr_done) {
        cudaFuncSetAttribute(hgemm_kernel<0,1>, cudaFuncAttributeMaxDynamicSharedMemorySize, HS_BYTES);
        cudaFuncSetAttribute(hgemm_kernel<2,0>, cudaFuncAttributeMaxDynamicSharedMemorySize, HS_BYTES);
        cudaFuncSetAttribute(hgemm_kernel<1,1>, cudaFuncAttributeMaxDynamicSharedMemorySize, HS_BYTES);
        attr_done = true;
    }

    float* out = (float*)d_out;

    dim3 t32(32, 8);
    // 1. batched weight staging (2 launches)
    wcast_sq_kernel<<<dim3(64, 16), t32>>>(Wq, Wk, Wv, Wo, pwqkv, pwo);
    wcast_mlp_kernel<<<1024, t32>>>(W1, W2, pw1, pw2);
    // 2. fused bias
    bcat_kernel<<<2, 256>>>(bq, bk, bv, pbqkv);
    // 3. z = LN1(x)  (bf16)
    ln_kernel<<<L_, 128>>>(x, ln1g, ln1b, pz);
    // 4. segment boundaries
    seg_kernel<<<E_ / 256, 256>>>(row, pseg);
    // 5. fused qkv projection  (launch #6 — ncu captures this)
    dim3 gQKV(QKV3 / 128, L_ / 128);
    hgemm_kernel<0, 1><<<gQKV, 256, HS_BYTES>>>(pz, pwqkv, pbqkv, nullptr, pqkv, L_, QKV3, C_);
    // 6. sparse attention
    attn_kernel<<<L_, 256>>>(pqkv, att_bias, col, pseg, pa);
    // 7. out = x + att @ Wo + bo
    dim3 gC(C_ / 128, L_ / 128);
    hgemm_kernel<2, 0><<<gC, 256, HS_BYTES>>>(pa, pwo, bo, x, out, L_, C_, C_);
    // 8. z = LN2(out)
    ln_kernel<<<L_, 128>>>(out, ln2g, ln2b, pz);
    // 9. h = silu(z @ W1 + b1)
    dim3 gH(HID_ / 128, L_ / 128);
    hgemm_kernel<1, 1><<<gH, 256, HS_BYTES>>>(pz, pw1, b1, nullptr, ph, L_, HID_, C_);
    // 10. out = out + h @ W2 + b2
    hgemm_kernel<2, 0><<<gC, 256, HS_BYTES>>>(ph, pw2, b2, out, out, L_, C_, HID_);
}